// round 13
// baseline (speedup 1.0000x reference)
#include <cuda_runtime.h>
#include <cuda_fp16.h>
#include <cstdint>

typedef unsigned short u16;
typedef unsigned int u32;

#define ORDER 256
#define HIDDEN 512
#define INPUT_DIM 256
#define BATCH 8192
#define TSTEPS 23
#define SLOPE 0.2f

#define KCH 64                      // K per pipeline chunk (one 128B row)
#define OPER_B (128 * 128)          // 16 KB per operand tile (128 rows x 128B)
#define STAGE_B (2 * OPER_B)        // A, B = 32 KB
#define NSTAGE 3
#define CS_STRIDE 132               // padded Cs row stride (conflict-free epilogue)
#define SMEM_H (NSTAGE * STAGE_B)                                   // 96 KB
#define SMEM_P (NSTAGE * STAGE_B + TSTEPS * CS_STRIDE * 4 + 184 * 4)
#define GRID_CTAS 256               // fused gemm_h grid (all co-resident at 2/SM)

// ---------------- scratch ----------------
__device__ float g_C[TSTEPS * HIDDEN];
__device__ float g_U[BATCH * TSTEPS];
__device__ float g_P[(size_t)BATCH * TSTEPS * HIDDEN];
__device__ __align__(16) u16 g_WhH[512 * 512];   // fp16, [n][k]
__device__ __align__(16) u16 g_WxH[512 * 256];   // fp16, [n][k] = Wx[k][n]
__device__ __align__(16) u16 g_Xf[(size_t)BATCH * TSTEPS * 256];  // fp16 X
__device__ __align__(16) u16 g_Hf0[BATCH * 512];                  // fp16 H ping
__device__ __align__(16) u16 g_Hf1[BATCH * 512];                  // fp16 H pong
__device__ u32 g_cnt = 0;          // grid barrier arrive counter
__device__ u32 g_gen = 0;          // grid barrier generation (monotonic, replay-safe)

// ---------------- low-level helpers ----------------
__device__ __forceinline__ u32 smem_u32(const void* p) {
    u32 a;
    asm("{ .reg .u64 t; cvta.to.shared.u64 t, %1; cvt.u32.u64 %0, t; }" : "=r"(a) : "l"(p));
    return a;
}
__device__ __forceinline__ u32 swz(u32 off) { return off ^ ((off >> 3) & 0x70); }

__device__ __forceinline__ void cp16(u32 dst, const void* src) {
    asm volatile("cp.async.cg.shared.global [%0], [%1], 16;" :: "r"(dst), "l"(src));
}
__device__ __forceinline__ void cp_commit() { asm volatile("cp.async.commit_group;" ::: "memory"); }
__device__ __forceinline__ void cp_wait1() { asm volatile("cp.async.wait_group 1;" ::: "memory"); }

__device__ __forceinline__ void ldsm4(u32* r, u32 a) {
    asm volatile("ldmatrix.sync.aligned.m8n8.x4.shared.b16 {%0,%1,%2,%3}, [%4];"
                 : "=r"(r[0]), "=r"(r[1]), "=r"(r[2]), "=r"(r[3]) : "r"(a));
}
__device__ __forceinline__ void mma_f32(float* d, const u32* a, u32 b0, u32 b1) {
    asm volatile(
        "mma.sync.aligned.m16n8k16.row.col.f32.f16.f16.f32 "
        "{%0,%1,%2,%3},{%4,%5,%6,%7},{%8,%9},{%0,%1,%2,%3};\n"
        : "+f"(d[0]), "+f"(d[1]), "+f"(d[2]), "+f"(d[3])
        : "r"(a[0]), "r"(a[1]), "r"(a[2]), "r"(a[3]), "r"(b0), "r"(b1));
}
__device__ __forceinline__ u32 pack_h2(float x0, float x1) {
    __half2 h = __floats2half2_rn(x0, x1);
    return *reinterpret_cast<u32*>(&h);
}
__device__ __forceinline__ u32 ld_acq(const u32* p) {
    u32 v;
    asm volatile("ld.acquire.gpu.global.u32 %0, [%1];" : "=r"(v) : "l"(p));
    return v;
}

// grid-wide barrier (all GRID_CTAS co-resident; generation-based, replay-safe)
__device__ __forceinline__ void grid_sync(u32 base_gen, int step, int tid) {
    __threadfence();
    __syncthreads();
    if (tid == 0) {
        u32 old = atomicAdd(&g_cnt, 1);
        if (old == GRID_CTAS - 1) {
            atomicExch(&g_cnt, 0);
            __threadfence();
            atomicAdd(&g_gen, 1);
        } else {
            u32 target = base_gen + (u32)step;
            while (ld_acq(&g_gen) < target) __nanosleep(64);
        }
    }
    __syncthreads();
}

// ---------------- generic stage loader (256 threads, A+B tiles 128x64 fp16) ----
__device__ __forceinline__ void stage_load(u32 sbase, int kdim,
                                           const u16* __restrict__ A, size_t aRowBase,
                                           const u16* __restrict__ B, int colBase,
                                           int k0, int tid) {
    #pragma unroll
    for (int j = 0; j < 4; j++) {
        int idx = j * 256 + tid;
        int row = idx >> 3, ch = idx & 7;
        u32 d = sbase + swz((u32)(row * 128 + ch * 16));
        cp16(d, A + (aRowBase + row) * kdim + k0 + ch * 8);
        cp16(d + OPER_B, B + (size_t)(colBase + row) * kdim + k0 + ch * 8);
    }
}

// ---------------- chunk compute (K=64: 4 k-steps), warp tile 32x64, 8 warps ----
__device__ __forceinline__ void compute_tile(u32 sbase, float accH[2][8][4],
                                             int wm, int wn, int lane) {
    u32 aB = sbase, bB = sbase + OPER_B;
    int rA = (lane & 7) + ((lane >> 3) & 1) * 8;
    int cA = lane >> 4;
    int rB = (lane & 7) + ((lane >> 4) << 3);
    int cB = (lane >> 3) & 1;
    #pragma unroll
    for (int ks = 0; ks < 4; ks++) {
        u32 af[2][4];
        #pragma unroll
        for (int mt = 0; mt < 2; mt++) {
            u32 off = swz((u32)((wm * 32 + mt * 16 + rA) * 128 + ks * 32 + cA * 16));
            ldsm4(af[mt], aB + off);
        }
        #pragma unroll
        for (int nh = 0; nh < 2; nh++) {
            #pragma unroll
            for (int q = 0; q < 2; q++) {
                u32 bf[4];
                u32 off = swz((u32)((wn * 64 + nh * 32 + q * 16 + rB) * 128 + ks * 32 + cB * 16));
                ldsm4(bf, bB + off);
                #pragma unroll
                for (int pb = 0; pb < 2; pb++) {
                    int nt = nh * 4 + q * 2 + pb;
                    #pragma unroll
                    for (int mt = 0; mt < 2; mt++)
                        mma_f32(accH[mt][nt], af[mt], bf[pb * 2], bf[pb * 2 + 1]);
                }
            }
        }
    }
}

// ---------------------------------------------------------------------------
// launch #1: u = x . e_x  AND  X -> fp16
// ---------------------------------------------------------------------------
__global__ void convX_U(const float* __restrict__ X, const float* __restrict__ ex) {
    __shared__ float se[INPUT_DIM];
    int tid = threadIdx.x;
    if (tid < INPUT_DIM) se[tid] = ex[tid];
    __syncthreads();
    int warp = tid >> 5, lane = tid & 31;
    size_t r = (size_t)blockIdx.x * 8 + warp;
    const float* xr = X + r * INPUT_DIM + lane * 8;
    float4 v0 = *(const float4*)(xr);
    float4 v1 = *(const float4*)(xr + 4);
    const float* er = se + lane * 8;
    float s = v0.x * er[0] + v0.y * er[1] + v0.z * er[2] + v0.w * er[3]
            + v1.x * er[4] + v1.y * er[5] + v1.z * er[6] + v1.w * er[7];
    #pragma unroll
    for (int o = 16; o; o >>= 1) s += __shfl_xor_sync(0xffffffffu, s, o);
    if (lane == 0) g_U[r] = s;
    uint4 h;
    h.x = pack_h2(v0.x, v0.y);
    h.y = pack_h2(v0.z, v0.w);
    h.z = pack_h2(v1.x, v1.y);
    h.w = pack_h2(v1.z, v1.w);
    *(uint4*)(g_Xf + r * INPUT_DIM + lane * 8) = h;
}

// ---------------------------------------------------------------------------
// launch #2 (fused prep): blocks [0,512) Wh->fp16; [512,768) Wx^T->fp16;
// block 768 computes C.  512 threads.
// ---------------------------------------------------------------------------
__global__ void prep_all(const float* __restrict__ Wh, const float* __restrict__ Wx,
                         const float* __restrict__ A, const float* __restrict__ Bv,
                         const float* __restrict__ Wm) {
    int tid = threadIdx.x;
    int b = blockIdx.x;
    if (b < 512) {
        int idx = b * 512 + tid;
        __half h = __float2half_rn(Wh[idx]);
        g_WhH[idx] = *reinterpret_cast<u16*>(&h);
        return;
    }
    if (b < 768) {
        int idx = (b - 512) * 512 + tid;
        int n = idx >> 8, k = idx & 255;
        __half h = __float2half_rn(Wx[k * 512 + n]);
        g_WxH[idx] = *reinterpret_cast<u16*>(&h);
        return;
    }
    __shared__ float v[2][ORDER];
    if (tid < ORDER) v[0][tid] = Bv[tid];
    __syncthreads();
    int cur = 0;
    for (int k = 0; k < TSTEPS; ++k) {
        float c = 0.f;
        const float* wrow = Wm + (size_t)tid * ORDER;
        #pragma unroll 8
        for (int i = 0; i < ORDER; ++i) c = fmaf(wrow[i], v[cur][i], c);
        g_C[k * HIDDEN + tid] = c;
        float nv = 0.f;
        if (tid < ORDER) {
            const float* arow = A + (size_t)tid * ORDER;
            #pragma unroll 8
            for (int i = 0; i < ORDER; ++i) nv = fmaf(arow[i], v[cur][i], nv);
        }
        __syncthreads();
        if (tid < ORDER) v[1 - cur][tid] = nv;
        cur ^= 1;
        __syncthreads();
    }
}

// ---------------------------------------------------------------------------
// launch #3: gemm_p. CTA 128x128, 256 thr, 2 CTA/SM, grid (1472, 4).
// ---------------------------------------------------------------------------
extern __shared__ char dsm[];
__global__ void __launch_bounds__(256, 2) gemm_p_v8(float* __restrict__ out) {
    u32 sb = smem_u32(dsm);
    float* Cs = (float*)(dsm + NSTAGE * STAGE_B);     // [23][CS_STRIDE]
    float* sU = Cs + TSTEPS * CS_STRIDE;              // [184]

    int tid = threadIdx.x, wid = tid >> 5, lane = tid & 31;
    int wm = wid & 3, wn = wid >> 2;
    int rowBase = blockIdx.x * 128, colBase = blockIdx.y * 128;
    int b0 = rowBase / TSTEPS;

    for (int i = tid; i < TSTEPS * 128; i += 256)
        Cs[(i >> 7) * CS_STRIDE + (i & 127)] = g_C[(i >> 7) * HIDDEN + colBase + (i & 127)];
    {
        int cnt = BATCH * TSTEPS - b0 * TSTEPS;
        if (cnt > 184) cnt = 184;
        for (int i = tid; i < cnt; i += 256) sU[i] = g_U[b0 * TSTEPS + i];
    }

    float accH[2][8][4];
    #pragma unroll
    for (int a = 0; a < 2; a++)
        #pragma unroll
        for (int b = 0; b < 8; b++)
            #pragma unroll
            for (int c = 0; c < 4; c++) accH[a][b][c] = 0.f;

    const int NCH = INPUT_DIM / KCH;   // 4
    stage_load(sb, INPUT_DIM, g_Xf, rowBase, g_WxH, colBase, 0, tid);
    cp_commit();
    stage_load(sb + STAGE_B, INPUT_DIM, g_Xf, rowBase, g_WxH, colBase, KCH, tid);
    cp_commit();

    int buf = 0;
    for (int c = 0; c < NCH; c++) {
        cp_wait1();
        __syncthreads();
        if (c + 2 < NCH) {
            int nb = buf + 2; if (nb >= NSTAGE) nb -= NSTAGE;
            stage_load(sb + nb * STAGE_B, INPUT_DIM, g_Xf, rowBase, g_WxH, colBase,
                       (c + 2) * KCH, tid);
        }
        cp_commit();
        compute_tile(sb + buf * STAGE_B, accH, wm, wn, lane);
        if (++buf == NSTAGE) buf = 0;
    }

    int quad = lane >> 2, tq = lane & 3;
    #pragma unroll
    for (int mt = 0; mt < 2; mt++) {
        #pragma unroll
        for (int h = 0; h < 2; h++) {
            int r = rowBase + wm * 32 + mt * 16 + quad + h * 8;
            int bb = r / TSTEPS;
            int tr = r - bb * TSTEPS;
            const float* u = sU + (bb - b0) * TSTEPS;
            float v[16];
            #pragma unroll
            for (int nt = 0; nt < 8; nt++) {
                v[2 * nt] = accH[mt][nt][h * 2];
                v[2 * nt + 1] = accH[mt][nt][h * 2 + 1];
            }
            for (int s = 0; s <= tr; ++s) {
                float us = u[s];
                const float* cp = Cs + (tr - s) * CS_STRIDE + wn * 64 + tq * 2;
                #pragma unroll
                for (int nt = 0; nt < 8; nt++) {
                    v[2 * nt] = fmaf(us, cp[nt * 8], v[2 * nt]);
                    v[2 * nt + 1] = fmaf(us, cp[nt * 8 + 1], v[2 * nt + 1]);
                }
            }
            if (tr == 0) {
                #pragma unroll
                for (int nt = 0; nt < 8; nt++) {
                    int cc = wn * 64 + nt * 8 + tq * 2;
                    size_t off = (size_t)r * HIDDEN + colBase + cc;
                    float h0 = v[2 * nt] >= 0.f ? v[2 * nt] : SLOPE * v[2 * nt];
                    float h1 = v[2 * nt + 1] >= 0.f ? v[2 * nt + 1] : SLOPE * v[2 * nt + 1];
                    *(float2*)(out + off) = make_float2(h0, h1);
                    *(u32*)(g_Hf0 + (size_t)bb * HIDDEN + colBase + cc) = pack_h2(h0, h1);
                }
            } else {
                #pragma unroll
                for (int nt = 0; nt < 8; nt++) {
                    int cc = wn * 64 + nt * 8 + tq * 2;
                    size_t off = (size_t)r * HIDDEN + colBase + cc;
                    *(float2*)(g_P + off) = make_float2(v[2 * nt], v[2 * nt + 1]);
                }
            }
        }
    }
}

// ---------------------------------------------------------------------------
// launch #4 (PROFILED): fused recurrence — ALL 22 steps in ONE persistent
// kernel.  grid (64,4)=256 CTAs, 256 thr, 2 CTA/SM (all co-resident),
// grid-wide barrier between steps.
// ---------------------------------------------------------------------------
__global__ void __launch_bounds__(256, 2) gemm_h_fused(float* __restrict__ out) {
    u32 sb = smem_u32(dsm);
    int tid = threadIdx.x, wid = tid >> 5, lane = tid & 31;
    int wm = wid & 3, wn = wid >> 2;
    int rowBase = blockIdx.x * 128, colBase = blockIdx.y * 128;
    int quad = lane >> 2, tq = lane & 3;

    u32 base_gen = 0;
    if (tid == 0) base_gen = ld_acq(&g_gen);

    for (int t = 1; t < TSTEPS; ++t) {
        const u16* Af = (t & 1) ? g_Hf0 : g_Hf1;   // t=1 reads Hf0 (written by gemm_p)
        u16* Df = (t & 1) ? g_Hf1 : g_Hf0;

        float accH[2][8][4];
        #pragma unroll
        for (int a = 0; a < 2; a++)
            #pragma unroll
            for (int b = 0; b < 8; b++)
                #pragma unroll
                for (int c = 0; c < 4; c++) accH[a][b][c] = 0.f;

        const int NCH = HIDDEN / KCH;   // 8
        stage_load(sb, HIDDEN, Af, rowBase, g_WhH, colBase, 0, tid);
        cp_commit();
        stage_load(sb + STAGE_B, HIDDEN, Af, rowBase, g_WhH, colBase, KCH, tid);
        cp_commit();

        int buf = 0;
        for (int c = 0; c < NCH; c++) {
            cp_wait1();
            __syncthreads();
            if (c + 2 < NCH) {
                int nb = buf + 2; if (nb >= NSTAGE) nb -= NSTAGE;
                stage_load(sb + nb * STAGE_B, HIDDEN, Af, rowBase, g_WhH, colBase,
                           (c + 2) * KCH, tid);
            }
            cp_commit();
            compute_tile(sb + buf * STAGE_B, accH, wm, wn, lane);
            if (++buf == NSTAGE) buf = 0;
        }

        #pragma unroll
        for (int mt = 0; mt < 2; mt++) {
            #pragma unroll
            for (int h = 0; h < 2; h++) {
                int m = rowBase + wm * 32 + mt * 16 + quad + h * 8;
                size_t off0 = ((size_t)m * TSTEPS + t) * HIDDEN + colBase;
                size_t hoff0 = (size_t)m * HIDDEN + colBase;
                #pragma unroll
                for (int nt = 0; nt < 8; nt++) {
                    int cc = wn * 64 + nt * 8 + tq * 2;
                    float2 p = *(const float2*)(g_P + off0 + cc);
                    float v0 = accH[mt][nt][h * 2] + p.x;
                    float v1 = accH[mt][nt][h * 2 + 1] + p.y;
                    v0 = v0 >= 0.f ? v0 : SLOPE * v0;
                    v1 = v1 >= 0.f ? v1 : SLOPE * v1;
                    *(float2*)(out + off0 + cc) = make_float2(v0, v1);
                    *(u32*)(Df + hoff0 + cc) = pack_h2(v0, v1);
                }
            }
        }

        if (t + 1 < TSTEPS) grid_sync(base_gen, t, tid);
    }
}

// ---------------------------------------------------------------------------
extern "C" void kernel_launch(void* const* d_in, const int* in_sizes, int n_in,
                              void* d_out, int out_size) {
    const float* X  = (const float*)d_in[0];
    const float* A  = (const float*)d_in[1];
    const float* Bv = (const float*)d_in[2];
    const float* Wh = (const float*)d_in[3];
    const float* Wm = (const float*)d_in[4];
    const float* Wx = (const float*)d_in[5];
    const float* ex = (const float*)d_in[6];
    float* out = (float*)d_out;

    cudaFuncSetAttribute(gemm_p_v8, cudaFuncAttributeMaxDynamicSharedMemorySize, SMEM_P);
    cudaFuncSetAttribute(gemm_h_fused, cudaFuncAttributeMaxDynamicSharedMemorySize, SMEM_H);

    convX_U<<<(BATCH * TSTEPS) / 8, 256>>>(X, ex);        // #1
    prep_all<<<769, 512>>>(Wh, Wx, A, Bv, Wm);            // #2
    dim3 gp((BATCH * TSTEPS) / 128, HIDDEN / 128);
    gemm_p_v8<<<gp, 256, SMEM_P>>>(out);                  // #3

    dim3 gh(BATCH / 128, HIDDEN / 128);                   // (64,4) = 256 CTAs
    gemm_h_fused<<<gh, 256, SMEM_H>>>(out);               // #4 <- ncu slot
}

// round 14
// speedup vs baseline: 1.1147x; 1.1147x over previous
#include <cuda_runtime.h>
#include <cuda_fp16.h>
#include <cstdint>

typedef unsigned short u16;
typedef unsigned int u32;

#define ORDER 256
#define HIDDEN 512
#define INPUT_DIM 256
#define BATCH 8192
#define TSTEPS 23
#define SLOPE 0.2f

#define KCH 64                      // K per pipeline chunk (one 128B row)
#define OPER_B (128 * 128)          // 16 KB per operand tile (128 rows x 128B)
#define STAGE_B (2 * OPER_B)        // A, B = 32 KB
#define NSTG 2
#define CS_STRIDE 132               // padded Cs row stride (conflict-free)
#define SMEM_F (NSTG * STAGE_B + TSTEPS * CS_STRIDE * 4 + 128 * TSTEPS * 4) // 89456
#define GRID_CTAS 256               // all co-resident at 2 CTA/SM (296 slots)

// ---------------- scratch ----------------
__device__ float g_C[TSTEPS * HIDDEN];
__device__ float g_U[BATCH * TSTEPS];
__device__ __align__(16) u16 g_WhH[512 * 512];   // fp16, [n][k]
__device__ __align__(16) u16 g_WxH[512 * 256];   // fp16, [n][k] = Wx[k][n]
__device__ __align__(16) u16 g_Xf[(size_t)BATCH * TSTEPS * 256];  // fp16 X
__device__ __align__(16) u16 g_Hf0[BATCH * 512];                  // fp16 H ping
__device__ __align__(16) u16 g_Hf1[BATCH * 512];                  // fp16 H pong
__device__ u32 g_cnt = 0;          // grid barrier arrive counter
__device__ u32 g_gen = 0;          // grid barrier generation (monotonic)

// ---------------- low-level helpers ----------------
__device__ __forceinline__ u32 smem_u32(const void* p) {
    u32 a;
    asm("{ .reg .u64 t; cvta.to.shared.u64 t, %1; cvt.u32.u64 %0, t; }" : "=r"(a) : "l"(p));
    return a;
}
__device__ __forceinline__ u32 swz(u32 off) { return off ^ ((off >> 3) & 0x70); }

__device__ __forceinline__ void cp16(u32 dst, const void* src) {
    asm volatile("cp.async.cg.shared.global [%0], [%1], 16;" :: "r"(dst), "l"(src));
}
__device__ __forceinline__ void cp_commit() { asm volatile("cp.async.commit_group;" ::: "memory"); }
__device__ __forceinline__ void cp_wait1() { asm volatile("cp.async.wait_group 1;" ::: "memory"); }

__device__ __forceinline__ void ldsm4(u32* r, u32 a) {
    asm volatile("ldmatrix.sync.aligned.m8n8.x4.shared.b16 {%0,%1,%2,%3}, [%4];"
                 : "=r"(r[0]), "=r"(r[1]), "=r"(r[2]), "=r"(r[3]) : "r"(a));
}
__device__ __forceinline__ void mma_f32(float* d, const u32* a, u32 b0, u32 b1) {
    asm volatile(
        "mma.sync.aligned.m16n8k16.row.col.f32.f16.f16.f32 "
        "{%0,%1,%2,%3},{%4,%5,%6,%7},{%8,%9},{%0,%1,%2,%3};\n"
        : "+f"(d[0]), "+f"(d[1]), "+f"(d[2]), "+f"(d[3])
        : "r"(a[0]), "r"(a[1]), "r"(a[2]), "r"(a[3]), "r"(b0), "r"(b1));
}
__device__ __forceinline__ u32 pack_h2(float x0, float x1) {
    __half2 h = __floats2half2_rn(x0, x1);
    return *reinterpret_cast<u32*>(&h);
}
__device__ __forceinline__ u32 ld_acq(const u32* p) {
    u32 v;
    asm volatile("ld.acquire.gpu.global.u32 %0, [%1];" : "=r"(v) : "l"(p));
    return v;
}

// grid-wide barrier (all GRID_CTAS co-resident; generation-based, replay-safe)
__device__ __forceinline__ void grid_sync(u32 base_gen, int step, int tid) {
    __threadfence();
    __syncthreads();
    if (tid == 0) {
        u32 old = atomicAdd(&g_cnt, 1);
        if (old == GRID_CTAS - 1) {
            atomicExch(&g_cnt, 0);
            __threadfence();
            atomicAdd(&g_gen, 1);
        } else {
            u32 target = base_gen + (u32)step;
            while (ld_acq(&g_gen) < target) __nanosleep(64);
        }
    }
    __syncthreads();
}

// ---------------- generic stage loader: A (arbitrary row stride) + B --------
__device__ __forceinline__ void load_AB(u32 sbase,
                                        const u16* __restrict__ Abase, size_t aStride,
                                        const u16* __restrict__ Bbase, int colBase,
                                        size_t bStride, int k0, int tid) {
    #pragma unroll
    for (int j = 0; j < 4; j++) {
        int idx = j * 256 + tid;
        int row = idx >> 3, ch = idx & 7;
        u32 d = sbase + swz((u32)(row * 128 + ch * 16));
        cp16(d, Abase + (size_t)row * aStride + k0 + ch * 8);
        cp16(d + OPER_B, Bbase + (size_t)(colBase + row) * bStride + k0 + ch * 8);
    }
}

// ---------------- chunk compute (K=64: 4 k-steps), warp tile 32x64, 8 warps ----
__device__ __forceinline__ void compute_tile(u32 sbase, float accH[2][8][4],
                                             int wm, int wn, int lane) {
    u32 aB = sbase, bB = sbase + OPER_B;
    int rA = (lane & 7) + ((lane >> 3) & 1) * 8;
    int cA = lane >> 4;
    int rB = (lane & 7) + ((lane >> 4) << 3);
    int cB = (lane >> 3) & 1;
    #pragma unroll
    for (int ks = 0; ks < 4; ks++) {
        u32 af[2][4];
        #pragma unroll
        for (int mt = 0; mt < 2; mt++) {
            u32 off = swz((u32)((wm * 32 + mt * 16 + rA) * 128 + ks * 32 + cA * 16));
            ldsm4(af[mt], aB + off);
        }
        #pragma unroll
        for (int nh = 0; nh < 2; nh++) {
            #pragma unroll
            for (int q = 0; q < 2; q++) {
                u32 bf[4];
                u32 off = swz((u32)((wn * 64 + nh * 32 + q * 16 + rB) * 128 + ks * 32 + cB * 16));
                ldsm4(bf, bB + off);
                #pragma unroll
                for (int pb = 0; pb < 2; pb++) {
                    int nt = nh * 4 + q * 2 + pb;
                    #pragma unroll
                    for (int mt = 0; mt < 2; mt++)
                        mma_f32(accH[mt][nt], af[mt], bf[pb * 2], bf[pb * 2 + 1]);
                }
            }
        }
    }
}

// ---------------------------------------------------------------------------
// launch #1: u = x . e_x  AND  X -> fp16
// ---------------------------------------------------------------------------
__global__ void convX_U(const float* __restrict__ X, const float* __restrict__ ex) {
    __shared__ float se[INPUT_DIM];
    int tid = threadIdx.x;
    if (tid < INPUT_DIM) se[tid] = ex[tid];
    __syncthreads();
    int warp = tid >> 5, lane = tid & 31;
    size_t r = (size_t)blockIdx.x * 8 + warp;
    const float* xr = X + r * INPUT_DIM + lane * 8;
    float4 v0 = *(const float4*)(xr);
    float4 v1 = *(const float4*)(xr + 4);
    const float* er = se + lane * 8;
    float s = v0.x * er[0] + v0.y * er[1] + v0.z * er[2] + v0.w * er[3]
            + v1.x * er[4] + v1.y * er[5] + v1.z * er[6] + v1.w * er[7];
    #pragma unroll
    for (int o = 16; o; o >>= 1) s += __shfl_xor_sync(0xffffffffu, s, o);
    if (lane == 0) g_U[r] = s;
    uint4 h;
    h.x = pack_h2(v0.x, v0.y);
    h.y = pack_h2(v0.z, v0.w);
    h.z = pack_h2(v1.x, v1.y);
    h.w = pack_h2(v1.z, v1.w);
    *(uint4*)(g_Xf + r * INPUT_DIM + lane * 8) = h;
}

// ---------------------------------------------------------------------------
// launch #2 (fused prep): Wh->fp16, Wx^T->fp16, C.
// ---------------------------------------------------------------------------
__global__ void prep_all(const float* __restrict__ Wh, const float* __restrict__ Wx,
                         const float* __restrict__ A, const float* __restrict__ Bv,
                         const float* __restrict__ Wm) {
    int tid = threadIdx.x;
    int b = blockIdx.x;
    if (b < 512) {
        int idx = b * 512 + tid;
        __half h = __float2half_rn(Wh[idx]);
        g_WhH[idx] = *reinterpret_cast<u16*>(&h);
        return;
    }
    if (b < 768) {
        int idx = (b - 512) * 512 + tid;
        int n = idx >> 8, k = idx & 255;
        __half h = __float2half_rn(Wx[k * 512 + n]);
        g_WxH[idx] = *reinterpret_cast<u16*>(&h);
        return;
    }
    __shared__ float v[2][ORDER];
    if (tid < ORDER) v[0][tid] = Bv[tid];
    __syncthreads();
    int cur = 0;
    for (int k = 0; k < TSTEPS; ++k) {
        float c = 0.f;
        const float* wrow = Wm + (size_t)tid * ORDER;
        #pragma unroll 8
        for (int i = 0; i < ORDER; ++i) c = fmaf(wrow[i], v[cur][i], c);
        g_C[k * HIDDEN + tid] = c;
        float nv = 0.f;
        if (tid < ORDER) {
            const float* arow = A + (size_t)tid * ORDER;
            #pragma unroll 8
            for (int i = 0; i < ORDER; ++i) nv = fmaf(arow[i], v[cur][i], nv);
        }
        __syncthreads();
        if (tid < ORDER) v[1 - cur][tid] = nv;
        cur ^= 1;
        __syncthreads();
    }
}

// ---------------------------------------------------------------------------
// launch #3: dummy (shifts the big kernel into the profiled #4 slot)
// ---------------------------------------------------------------------------
__global__ void dummy_shift() {}

// ---------------------------------------------------------------------------
// launch #4 (PROFILED): full LMU — all 23 steps, ONE persistent kernel.
// Step t: acc = (t>0 ? H_{t-1}@Wh^T : 0) + X_t@Wx ; epilogue adds
// triangular sum_{s<=t} u_s C_{t-s}, lrelu, writes out_t (fp32) + Hf (fp16).
// grid (64,4)=256 CTAs, 256 thr, 2 CTA/SM, grid barrier between steps.
// ---------------------------------------------------------------------------
extern __shared__ char dsm[];
__global__ void __launch_bounds__(256, 2) lmu_fused(float* __restrict__ out) {
    u32 sb = smem_u32(dsm);
    float* Cs = (float*)(dsm + NSTG * STAGE_B);       // [23][CS_STRIDE]
    float* sU = Cs + TSTEPS * CS_STRIDE;              // [128][23]

    int tid = threadIdx.x, wid = tid >> 5, lane = tid & 31;
    int wm = wid & 3, wn = wid >> 2;                  // 4x2 warps, warp 32x64
    int rowBase = blockIdx.x * 128, colBase = blockIdx.y * 128;
    int quad = lane >> 2, tq = lane & 3;

    // stage constants once
    for (int i = tid; i < TSTEPS * 128; i += 256)
        Cs[(i >> 7) * CS_STRIDE + (i & 127)] = g_C[(i >> 7) * HIDDEN + colBase + (i & 127)];
    for (int i = tid; i < 128 * TSTEPS; i += 256)
        sU[i] = g_U[(size_t)(rowBase + (i / TSTEPS)) * TSTEPS + (i % TSTEPS)];

    u32 base_gen = 0;
    if (tid == 0) base_gen = ld_acq(&g_gen);
    __syncthreads();

    for (int t = 0; t < TSTEPS; ++t) {
        const u16* Af = (t & 1) ? g_Hf0 : g_Hf1;   // step t reads Df(t-1)
        u16* Df = (t & 1) ? g_Hf1 : g_Hf0;
        const u16* Xrow = g_Xf + ((size_t)rowBase * TSTEPS + t) * INPUT_DIM;

        float accH[2][8][4];
        #pragma unroll
        for (int a = 0; a < 2; a++)
            #pragma unroll
            for (int b = 0; b < 8; b++)
                #pragma unroll
                for (int c = 0; c < 4; c++) accH[a][b][c] = 0.f;

        // chunk schedule: t>0: chunks 0..7 = Wh(K=512), 8..11 = Wx(K=256);
        //                 t==0: chunks 0..3 = Wx only.
        const int NCH = (t == 0) ? 4 : 12;
        #define LOAD_CHUNK(buf_addr, cc)                                              \
            do {                                                                      \
                int _c = (cc);                                                        \
                if (t > 0 && _c < 8)                                                  \
                    load_AB((buf_addr), Af + (size_t)rowBase * HIDDEN, HIDDEN,        \
                            g_WhH, colBase, HIDDEN, _c * KCH, tid);                   \
                else {                                                                \
                    int _cx = (t > 0) ? _c - 8 : _c;                                  \
                    load_AB((buf_addr), Xrow, (size_t)TSTEPS * INPUT_DIM,             \
                            g_WxH, colBase, INPUT_DIM, _cx * KCH, tid);               \
                }                                                                     \
            } while (0)

        LOAD_CHUNK(sb, 0);
        cp_commit();
        LOAD_CHUNK(sb + STAGE_B, 1);
        cp_commit();

        for (int c = 0; c < NCH; c++) {
            cp_wait1();
            __syncthreads();
            compute_tile(sb + (c & 1) * STAGE_B, accH, wm, wn, lane);
            __syncthreads();
            if (c + 2 < NCH) LOAD_CHUNK(sb + (c & 1) * STAGE_B, c + 2);
            cp_commit();
        }
        #undef LOAD_CHUNK

        // epilogue: + triangular U*C, lrelu, store out (fp32) and Hf (fp16)
        #pragma unroll
        for (int mt = 0; mt < 2; mt++) {
            #pragma unroll
            for (int h = 0; h < 2; h++) {
                int rl = wm * 32 + mt * 16 + quad + h * 8;   // local batch row
                int m = rowBase + rl;
                const float* u = sU + rl * TSTEPS;
                float v[16];
                #pragma unroll
                for (int nt = 0; nt < 8; nt++) {
                    v[2 * nt] = accH[mt][nt][h * 2];
                    v[2 * nt + 1] = accH[mt][nt][h * 2 + 1];
                }
                for (int s = 0; s <= t; ++s) {
                    float us = u[s];
                    const float* cp = Cs + (t - s) * CS_STRIDE + wn * 64 + tq * 2;
                    #pragma unroll
                    for (int nt = 0; nt < 8; nt++) {
                        v[2 * nt] = fmaf(us, cp[nt * 8], v[2 * nt]);
                        v[2 * nt + 1] = fmaf(us, cp[nt * 8 + 1], v[2 * nt + 1]);
                    }
                }
                size_t off0 = ((size_t)m * TSTEPS + t) * HIDDEN + colBase;
                size_t hoff0 = (size_t)m * HIDDEN + colBase;
                #pragma unroll
                for (int nt = 0; nt < 8; nt++) {
                    int cc = wn * 64 + nt * 8 + tq * 2;
                    float v0 = v[2 * nt], v1 = v[2 * nt + 1];
                    v0 = v0 >= 0.f ? v0 : SLOPE * v0;
                    v1 = v1 >= 0.f ? v1 : SLOPE * v1;
                    *(float2*)(out + off0 + cc) = make_float2(v0, v1);
                    *(u32*)(Df + hoff0 + cc) = pack_h2(v0, v1);
                }
            }
        }

        if (t + 1 < TSTEPS) grid_sync(base_gen, t + 1, tid);
    }
}

// ---------------------------------------------------------------------------
extern "C" void kernel_launch(void* const* d_in, const int* in_sizes, int n_in,
                              void* d_out, int out_size) {
    const float* X  = (const float*)d_in[0];
    const float* A  = (const float*)d_in[1];
    const float* Bv = (const float*)d_in[2];
    const float* Wh = (const float*)d_in[3];
    const float* Wm = (const float*)d_in[4];
    const float* Wx = (const float*)d_in[5];
    const float* ex = (const float*)d_in[6];
    float* out = (float*)d_out;

    cudaFuncSetAttribute(lmu_fused, cudaFuncAttributeMaxDynamicSharedMemorySize, SMEM_F);

    convX_U<<<(BATCH * TSTEPS) / 8, 256>>>(X, ex);        // #1
    prep_all<<<769, 512>>>(Wh, Wx, A, Bv, Wm);            // #2
    dummy_shift<<<1, 32>>>();                             // #3
    dim3 gf(BATCH / 128, HIDDEN / 128);                   // (64,4) = 256 CTAs
    lmu_fused<<<gf, 256, SMEM_F>>>(out);                  // #4 <- ncu slot
}